// round 11
// baseline (speedup 1.0000x reference)
#include <cuda_runtime.h>
#include <cuda_fp16.h>
#include <stdint.h>

#define BATCHN 65536
#define NROWS  (BATCHN * 8)
#define NGRP   8192
#define OBSD   114

__device__ __forceinline__ float fast_tanh(float x){float y;asm("tanh.approx.f32 %0,%1;":"=f"(y):"f"(x));return y;}
// accurate tanh, 1 MUFU (EX2) + Newton reciprocal on FMA/ALU pipes (rel err ~1e-9 on 1/y)
__device__ __forceinline__ float tanh_acc(float x){
    float u = fminf(__expf(2.f * x), 1e8f);     // clamp: tanh saturates anyway
    float y = 1.f + u;
    float r = __uint_as_float(0x7EF0A3D7u - __float_as_uint(y));
    r = r * (2.f - y * r);
    r = r * (2.f - y * r);
    r = r * (2.f - y * r);
    return fmaf(-2.f, r, 1.f);
}
__device__ __forceinline__ uint32_t pack2(float a, float b){ __half2 h = __floats2half2_rn(a, b); return *(uint32_t*)&h; }

__device__ __forceinline__ void mma16(float c[4], uint32_t a0, uint32_t a1, uint32_t a2, uint32_t a3,
                                      uint32_t b0, uint32_t b1){
    asm volatile("mma.sync.aligned.m16n8k16.row.col.f32.f16.f16.f32 "
                 "{%0,%1,%2,%3},{%4,%5,%6,%7},{%8,%9},{%0,%1,%2,%3};"
                 : "+f"(c[0]), "+f"(c[1]), "+f"(c[2]), "+f"(c[3])
                 : "r"(a0), "r"(a1), "r"(a2), "r"(a3), "r"(b0), "r"(b1));
}

// Full-width layer: warp's 16 rows x 128 cols. A-fragments af[ks][4] in regs.
template<int KS>
__device__ __forceinline__ void mma_reg(const uint32_t af[][4], const uint4* __restrict__ Wp,
                                        float acc[16][4], int lane){
    #pragma unroll
    for (int nt = 0; nt < 16; nt++){ acc[nt][0]=acc[nt][1]=acc[nt][2]=acc[nt][3]=0.f; }
    #pragma unroll
    for (int ks = 0; ks < KS; ks++){
        #pragma unroll
        for (int ntp = 0; ntp < 8; ntp++){
            uint4 b = Wp[ks * 256 + ntp * 32 + lane];
            mma16(acc[2*ntp],   af[ks][0], af[ks][1], af[ks][2], af[ks][3], b.x, b.y);
            mma16(acc[2*ntp+1], af[ks][0], af[ks][1], af[ks][2], af[ks][3], b.z, b.w);
        }
    }
}

// acc(+bias) -> fast tanh -> repack as next layer's A-fragments (in registers).
__device__ __forceinline__ void transition(const float acc[16][4], uint32_t af[8][4],
                                           const float* __restrict__ bias, int t){
    #pragma unroll
    for (int ks = 0; ks < 8; ks++){
        int c0 = (2*ks) * 8 + 2 * t, c1 = c0 + 8;
        float b00 = bias[c0], b01 = bias[c0 + 1];
        float b10 = bias[c1], b11 = bias[c1 + 1];
        af[ks][0] = pack2(fast_tanh(acc[2*ks][0] + b00),   fast_tanh(acc[2*ks][1] + b01));
        af[ks][1] = pack2(fast_tanh(acc[2*ks][2] + b00),   fast_tanh(acc[2*ks][3] + b01));
        af[ks][2] = pack2(fast_tanh(acc[2*ks+1][0] + b10), fast_tanh(acc[2*ks+1][1] + b11));
        af[ks][3] = pack2(fast_tanh(acc[2*ks+1][2] + b10), fast_tanh(acc[2*ks+1][3] + b11));
    }
}

// Pack W[k][n] (row-major K x 128 fp32) into uint4 B-fragment-pair order.
__device__ __forceinline__ void pack_w4(const float* __restrict__ W, uint4* __restrict__ Wp,
                                        int KS, int K, int tid, int nthr){
    for (int f = tid; f < KS * 8 * 32; f += nthr){
        int ks = f >> 8, ntp = (f >> 5) & 7, lane = f & 31;
        int g = lane >> 2, t = lane & 3;
        int n0 = ntp * 16 + g, n1 = n0 + 8;
        int k0 = ks * 16 + 2 * t, k1 = k0 + 8;
        float a00 = (k0     < K) ? W[(size_t)k0       * 128 + n0] : 0.f;
        float a01 = (k0 + 1 < K) ? W[(size_t)(k0 + 1) * 128 + n0] : 0.f;
        float a10 = (k1     < K) ? W[(size_t)k1       * 128 + n0] : 0.f;
        float a11 = (k1 + 1 < K) ? W[(size_t)(k1 + 1) * 128 + n0] : 0.f;
        float b00 = (k0     < K) ? W[(size_t)k0       * 128 + n1] : 0.f;
        float b01 = (k0 + 1 < K) ? W[(size_t)(k0 + 1) * 128 + n1] : 0.f;
        float b10 = (k1     < K) ? W[(size_t)k1       * 128 + n1] : 0.f;
        float b11 = (k1 + 1 < K) ? W[(size_t)(k1 + 1) * 128 + n1] : 0.f;
        Wp[f] = make_uint4(pack2(a00, a01), pack2(a10, a11), pack2(b00, b01), pack2(b10, b11));
    }
}

// smem offsets (fused)
#define F_W1E  0
#define F_W2E  8192
#define F_W1V  40960
#define F_W2V  73728
#define F_BS   106496
#define F_STG  108544
#define F_SMEM 123904   // + 12 warps * 16 rows * 40 halves * 2B

// ============================================================================
// FUSED: gather -> embed MLP -> attn -> value MLP -> combine -> AA.
// Warp owns a 16-row slab (2 batches), all 128 cols; barrier-free main loop.
// lane = g*4 + t (g = row-in-8-group / neighbor id, t = k-quarter).
// ============================================================================
__global__ void __launch_bounds__(384, 1)
fused_ev_kernel(const float* __restrict__ obs,
                const float* __restrict__ eW1, const float* __restrict__ eb1,
                const float* __restrict__ eW2, const float* __restrict__ eb2,
                const float* __restrict__ vW1, const float* __restrict__ vb1,
                const float* __restrict__ vW2, const float* __restrict__ vb2,
                float* __restrict__ AA)
{
    extern __shared__ char sm[];
    uint4* W1E = (uint4*)(sm + F_W1E);
    uint4* W2E = (uint4*)(sm + F_W2E);
    uint4* W1V = (uint4*)(sm + F_W1V);
    uint4* W2V = (uint4*)(sm + F_W2V);
    float* bs  = (float*)(sm + F_BS);

    const int tid = threadIdx.x, w = tid >> 5, lane = tid & 31;
    const int g = lane >> 2, t = lane & 3;

    pack_w4(eW1, W1E, 2, 30, tid, 384);
    pack_w4(eW2, W2E, 8, 128, tid, 384);
    pack_w4(vW1, W1V, 8, 128, tid, 384);
    pack_w4(vW2, W2V, 8, 128, tid, 384);
    if (tid < 128){
        bs[tid] = eb1[tid]; bs[128 + tid] = eb2[tid];
        bs[256 + tid] = vb1[tid]; bs[384 + tid] = vb2[tid];
    }
    __syncthreads();

    __half* stg = (__half*)(sm + F_STG) + w * 16 * 40;   // 40-half rows: conflict-free frags
    const float qs = 0.011048543456039806f;              // 1/(8*sqrt(128))
    const int NSLAB = NROWS / 16;                        // 32768
    const int step  = gridDim.x * 12;

    for (int slab = blockIdx.x * 12 + w; slab < NSLAB; slab += step){
        const int row0 = slab * 16;

        {   // ---- gather 16 rows x 32 cols (cols>=30 zero) into stage ----
            int r = lane >> 1, q = lane & 1;
            int R = row0 + r;
            const float* sp = obs + (size_t)(R & (BATCHN - 1)) * OBSD;
            const float* np = obs + (size_t)(R >> 3) * OBSD + 18 + (R & 7) * 12;
            uint32_t h[8];
            #pragma unroll
            for (int jj = 0; jj < 8; jj++){
                int c = q * 16 + 2 * jj;
                float v0 = (c     < 18) ? sp[c]     : ((c     < 30) ? np[c - 18] : 0.f);
                float v1 = (c + 1 < 18) ? sp[c + 1] : ((c + 1 < 30) ? np[c - 17] : 0.f);
                h[jj] = pack2(v0, v1);
            }
            *(uint4*)(stg + r * 40 + q * 16)     = make_uint4(h[0], h[1], h[2], h[3]);
            *(uint4*)(stg + r * 40 + q * 16 + 8) = make_uint4(h[4], h[5], h[6], h[7]);
        }
        __syncwarp();

        // ---- embed L1 (K=32): A-frags from stage ----
        uint32_t af1[2][4];
        {
            const __half* s0 = stg + g * 40;
            const __half* s1 = stg + (g + 8) * 40;
            #pragma unroll
            for (int ks = 0; ks < 2; ks++){
                af1[ks][0] = *(const uint32_t*)(s0 + ks * 16 + 2 * t);
                af1[ks][1] = *(const uint32_t*)(s1 + ks * 16 + 2 * t);
                af1[ks][2] = *(const uint32_t*)(s0 + ks * 16 + 2 * t + 8);
                af1[ks][3] = *(const uint32_t*)(s1 + ks * 16 + 2 * t + 8);
            }
        }
        float acc[16][4];
        uint32_t af[8][4];
        mma_reg<2>(af1, W1E, acc, lane);
        transition(acc, af, bs, t);            // h1 -> af
        mma_reg<8>(af, W2E, acc, lane);        // embed L2
        transition(acc, af, bs + 128, t);      // e -> af (fp16, stays in regs)

        // ---- attention weights from e (af) via g-dim shuffles ----
        float wA, wB;
        {
            float fa[32];
            #pragma unroll
            for (int ks = 0; ks < 8; ks++){
                float2 u0 = __half22float2(*(__half2*)&af[ks][0]);
                float2 u2 = __half22float2(*(__half2*)&af[ks][2]);
                fa[4*ks]=u0.x; fa[4*ks+1]=u0.y; fa[4*ks+2]=u2.x; fa[4*ks+3]=u2.y;
            }
            #pragma unroll
            for (int o = 4; o <= 16; o <<= 1)
                #pragma unroll
                for (int i = 0; i < 32; i++) fa[i] += __shfl_xor_sync(0xffffffff, fa[i], o);
            float sA = 0.f;
            #pragma unroll
            for (int ks = 0; ks < 8; ks++){
                float2 u0 = __half22float2(*(__half2*)&af[ks][0]);
                float2 u2 = __half22float2(*(__half2*)&af[ks][2]);
                sA += fa[4*ks]*u0.x + fa[4*ks+1]*u0.y + fa[4*ks+2]*u2.x + fa[4*ks+3]*u2.y;
            }
            sA *= qs;
            sA += __shfl_xor_sync(0xffffffff, sA, 1);
            sA += __shfl_xor_sync(0xffffffff, sA, 2);
            #pragma unroll
            for (int ks = 0; ks < 8; ks++){
                float2 u1 = __half22float2(*(__half2*)&af[ks][1]);
                float2 u3 = __half22float2(*(__half2*)&af[ks][3]);
                fa[4*ks]=u1.x; fa[4*ks+1]=u1.y; fa[4*ks+2]=u3.x; fa[4*ks+3]=u3.y;
            }
            #pragma unroll
            for (int o = 4; o <= 16; o <<= 1)
                #pragma unroll
                for (int i = 0; i < 32; i++) fa[i] += __shfl_xor_sync(0xffffffff, fa[i], o);
            float sB = 0.f;
            #pragma unroll
            for (int ks = 0; ks < 8; ks++){
                float2 u1 = __half22float2(*(__half2*)&af[ks][1]);
                float2 u3 = __half22float2(*(__half2*)&af[ks][3]);
                sB += fa[4*ks]*u1.x + fa[4*ks+1]*u1.y + fa[4*ks+2]*u3.x + fa[4*ks+3]*u3.y;
            }
            sB *= qs;
            sB += __shfl_xor_sync(0xffffffff, sB, 1);
            sB += __shfl_xor_sync(0xffffffff, sB, 2);
            float mxA = sA, mxB = sB;
            #pragma unroll
            for (int o = 4; o <= 16; o <<= 1){
                mxA = fmaxf(mxA, __shfl_xor_sync(0xffffffff, mxA, o));
                mxB = fmaxf(mxB, __shfl_xor_sync(0xffffffff, mxB, o));
            }
            float eA = __expf(sA - mxA), eB = __expf(sB - mxB);
            float uA = eA, uB = eB;
            #pragma unroll
            for (int o = 4; o <= 16; o <<= 1){
                uA += __shfl_xor_sync(0xffffffff, uA, o);
                uB += __shfl_xor_sync(0xffffffff, uB, o);
            }
            wA = eA / uA; wB = eB / uB;
        }

        // ---- value MLP on e ----
        mma_reg<8>(af, W1V, acc, lane);
        transition(acc, af, bs + 256, t);      // h2 -> af
        mma_reg<8>(af, W2V, acc, lane);

        // ---- v = tanh_acc(acc+b2); weighted sum over neighbors (g-dim) -> AA ----
        #pragma unroll
        for (int nt = 0; nt < 16; nt++){
            int c = nt * 8 + 2 * t;
            float b0 = bs[384 + c], b1 = bs[384 + c + 1];
            acc[nt][0] = tanh_acc(acc[nt][0] + b0) * wA;
            acc[nt][1] = tanh_acc(acc[nt][1] + b1) * wA;
            acc[nt][2] = tanh_acc(acc[nt][2] + b0) * wB;
            acc[nt][3] = tanh_acc(acc[nt][3] + b1) * wB;
        }
        #pragma unroll
        for (int o = 4; o <= 16; o <<= 1)
            #pragma unroll
            for (int nt = 0; nt < 16; nt++){
                acc[nt][0] += __shfl_xor_sync(0xffffffff, acc[nt][0], o);
                acc[nt][1] += __shfl_xor_sync(0xffffffff, acc[nt][1], o);
                acc[nt][2] += __shfl_xor_sync(0xffffffff, acc[nt][2], o);
                acc[nt][3] += __shfl_xor_sync(0xffffffff, acc[nt][3], o);
            }
        float* outA = AA + (size_t)(slab * 2) * 128;
        if (lane < 4){
            #pragma unroll
            for (int nt = 0; nt < 16; nt++)
                *(float2*)(outA + nt * 8 + 2 * t) = make_float2(acc[nt][0], acc[nt][1]);
        } else if (lane < 8){
            #pragma unroll
            for (int nt = 0; nt < 16; nt++)
                *(float2*)(outA + 128 + nt * 8 + 2 * t) = make_float2(acc[nt][2], acc[nt][3]);
        }
    }
}

// smem offsets (agent+mha)
#define A_W1   0
#define A_W2   32768
#define A_BS   65536
#define A_SMEM 66560

// ============================================================================
// MERGED agent MLP + multi-head attention.
// Warp slab = 16 AA rows = groups (2s, 2s+1). Scores from af (K) computed
// BEFORE the MLP consumes it; V stays fp32 in acc; per-head softmax over the
// g-dim; lane (g,t) writes tiled-copy g of the output.
// ============================================================================
__global__ void __launch_bounds__(384, 1)
agent_mha_kernel(const float* __restrict__ X,
                 const float* __restrict__ W1, const float* __restrict__ b1,
                 const float* __restrict__ W2, const float* __restrict__ b2,
                 float* __restrict__ out)
{
    extern __shared__ char sm[];
    uint4* Wp1 = (uint4*)(sm + A_W1);
    uint4* Wp2 = (uint4*)(sm + A_W2);
    float* bs  = (float*)(sm + A_BS);

    const int tid = threadIdx.x, w = tid >> 5, lane = tid & 31;
    const int g = lane >> 2, t = lane & 3;

    pack_w4(W1, Wp1, 8, 128, tid, 384);
    pack_w4(W2, Wp2, 8, 128, tid, 384);
    if (tid < 128){ bs[tid] = b1[tid]; bs[128 + tid] = b2[tid]; }
    __syncthreads();

    const int NSLAB = BATCHN / 16;            // 4096
    const int step  = gridDim.x * 12;

    for (int slab = blockIdx.x * 12 + w; slab < NSLAB; slab += step){
        const int row0 = slab * 16;
        uint32_t af[8][4];
        {   // A-frags straight from gmem (float2 pairs)
            const float2* pA = (const float2*)(X + (size_t)(row0 + g) * 128);
            const float2* pB = (const float2*)(X + (size_t)(row0 + g + 8) * 128);
            #pragma unroll
            for (int ks = 0; ks < 8; ks++){
                float2 a0 = pA[ks * 8 + t],     b0v = pB[ks * 8 + t];
                float2 a2 = pA[ks * 8 + t + 4], b2v = pB[ks * 8 + t + 4];
                af[ks][0] = pack2(a0.x, a0.y);
                af[ks][1] = pack2(b0v.x, b0v.y);
                af[ks][2] = pack2(a2.x, a2.y);
                af[ks][3] = pack2(b2v.x, b2v.y);
            }
        }

        // ---- MHA weights per head (from af = K, before MLP overwrites it) ----
        float wAh[8], wBh[8];
        {
            float sA[8], sB[8];
            #pragma unroll
            for (int h = 0; h < 8; h++){
                float2 f0 = __half22float2(*(__half2*)&af[h][0]);
                float2 f2 = __half22float2(*(__half2*)&af[h][2]);
                float2 g1 = __half22float2(*(__half2*)&af[h][1]);
                float2 g3 = __half22float2(*(__half2*)&af[h][3]);
                float qa0 = f0.x, qa1 = f0.y, qa2 = f2.x, qa3 = f2.y;
                float qb0 = g1.x, qb1 = g1.y, qb2 = g3.x, qb3 = g3.y;
                #pragma unroll
                for (int o = 4; o <= 16; o <<= 1){
                    qa0 += __shfl_xor_sync(0xffffffff, qa0, o);
                    qa1 += __shfl_xor_sync(0xffffffff, qa1, o);
                    qa2 += __shfl_xor_sync(0xffffffff, qa2, o);
                    qa3 += __shfl_xor_sync(0xffffffff, qa3, o);
                    qb0 += __shfl_xor_sync(0xffffffff, qb0, o);
                    qb1 += __shfl_xor_sync(0xffffffff, qb1, o);
                    qb2 += __shfl_xor_sync(0xffffffff, qb2, o);
                    qb3 += __shfl_xor_sync(0xffffffff, qb3, o);
                }
                float pa = qa0*f0.x + qa1*f0.y + qa2*f2.x + qa3*f2.y;
                float pb = qb0*g1.x + qb1*g1.y + qb2*g3.x + qb3*g3.y;
                pa += __shfl_xor_sync(0xffffffff, pa, 1);
                pa += __shfl_xor_sync(0xffffffff, pa, 2);
                pb += __shfl_xor_sync(0xffffffff, pb, 1);
                pb += __shfl_xor_sync(0xffffffff, pb, 2);
                sA[h] = pa * 0.03125f;        // mean(1/8) * rsqrt(16)
                sB[h] = pb * 0.03125f;
            }
            #pragma unroll
            for (int h = 0; h < 8; h++){
                float mA = sA[h], mB = sB[h];
                #pragma unroll
                for (int o = 4; o <= 16; o <<= 1){
                    mA = fmaxf(mA, __shfl_xor_sync(0xffffffff, mA, o));
                    mB = fmaxf(mB, __shfl_xor_sync(0xffffffff, mB, o));
                }
                float eA = __expf(sA[h] - mA), eB = __expf(sB[h] - mB);
                float uA = eA, uB = eB;
                #pragma unroll
                for (int o = 4; o <= 16; o <<= 1){
                    uA += __shfl_xor_sync(0xffffffff, uA, o);
                    uB += __shfl_xor_sync(0xffffffff, uB, o);
                }
                wAh[h] = __fdividef(eA, uA);
                wBh[h] = __fdividef(eB, uB);
            }
        }

        // ---- agent MLP (register-chained) ----
        float acc[16][4];
        mma_reg<8>(af, Wp1, acc, lane);
        transition(acc, af, bs, t);
        mma_reg<8>(af, Wp2, acc, lane);

        // ---- v = tanh_acc(acc+b2); per-head weighted sum over agents ----
        #pragma unroll
        for (int nt = 0; nt < 16; nt++){
            int h = nt >> 1;
            int c = nt * 8 + 2 * t;
            float b0 = bs[128 + c], b1v = bs[128 + c + 1];
            acc[nt][0] = tanh_acc(acc[nt][0] + b0)  * wAh[h];
            acc[nt][1] = tanh_acc(acc[nt][1] + b1v) * wAh[h];
            acc[nt][2] = tanh_acc(acc[nt][2] + b0)  * wBh[h];
            acc[nt][3] = tanh_acc(acc[nt][3] + b1v) * wBh[h];
        }
        #pragma unroll
        for (int o = 4; o <= 16; o <<= 1)
            #pragma unroll
            for (int nt = 0; nt < 16; nt++){
                acc[nt][0] += __shfl_xor_sync(0xffffffff, acc[nt][0], o);
                acc[nt][1] += __shfl_xor_sync(0xffffffff, acc[nt][1], o);
                acc[nt][2] += __shfl_xor_sync(0xffffffff, acc[nt][2], o);
                acc[nt][3] += __shfl_xor_sync(0xffffffff, acc[nt][3], o);
            }

        // ---- write: lane (g,t) writes tiled copy g for both groups ----
        const int ga = slab * 2, gb = ga + 1;
        float* oA = out + ((size_t)g * NGRP + ga) * 128;
        float* oB = out + ((size_t)g * NGRP + gb) * 128;
        #pragma unroll
        for (int nt = 0; nt < 16; nt++){
            *(float2*)(oA + nt * 8 + 2 * t) = make_float2(acc[nt][0], acc[nt][1]);
            *(float2*)(oB + nt * 8 + 2 * t) = make_float2(acc[nt][2], acc[nt][3]);
        }
    }
}

// ============================================================================
extern "C" void kernel_launch(void* const* d_in, const int* in_sizes, int n_in,
                              void* d_out, int out_size)
{
    const float* obs = (const float*)d_in[0];
    const float* eW1 = (const float*)d_in[1];
    const float* eb1 = (const float*)d_in[2];
    const float* eW2 = (const float*)d_in[3];
    const float* eb2 = (const float*)d_in[4];
    const float* vW1 = (const float*)d_in[5];
    const float* vb1 = (const float*)d_in[6];
    const float* vW2 = (const float*)d_in[7];
    const float* vb2 = (const float*)d_in[8];
    const float* aW1 = (const float*)d_in[9];
    const float* ab1 = (const float*)d_in[10];
    const float* aW2 = (const float*)d_in[11];
    const float* ab2 = (const float*)d_in[12];

    float* out = (float*)d_out;                 // multi_head_attention
    float* AA  = out + (size_t)BATCHN * 128;    // agent_attention

    cudaFuncSetAttribute(fused_ev_kernel,  cudaFuncAttributeMaxDynamicSharedMemorySize, F_SMEM);
    cudaFuncSetAttribute(agent_mha_kernel, cudaFuncAttributeMaxDynamicSharedMemorySize, A_SMEM);

    fused_ev_kernel<<<148, 384, F_SMEM>>>(obs, eW1, eb1, eW2, eb2,
                                          vW1, vb1, vW2, vb2, AA);
    agent_mha_kernel<<<148, 384, A_SMEM>>>(AA, aW1, ab1, aW2, ab2, out);
}

// round 12
// speedup vs baseline: 1.0964x; 1.0964x over previous
#include <cuda_runtime.h>
#include <cuda_fp16.h>
#include <stdint.h>

#define BATCHN 65536
#define NROWS  (BATCHN * 8)
#define NGRP   8192
#define OBSD   114

__device__ __half g_av[(size_t)BATCHN * 128];   // agent values, fp16 (16 MB)

__device__ __forceinline__ float fast_tanh(float x){float y;asm("tanh.approx.f32 %0,%1;":"=f"(y):"f"(x));return y;}
__device__ __forceinline__ float tanh_acc(float x){ return 1.f - __fdividef(2.f, __expf(2.f * x) + 1.f); }
__device__ __forceinline__ uint32_t pack2(float a, float b){ __half2 h = __floats2half2_rn(a, b); return *(uint32_t*)&h; }

__device__ __forceinline__ void mma16(float c[4], uint32_t a0, uint32_t a1, uint32_t a2, uint32_t a3,
                                      uint32_t b0, uint32_t b1){
    asm volatile("mma.sync.aligned.m16n8k16.row.col.f32.f16.f16.f32 "
                 "{%0,%1,%2,%3},{%4,%5,%6,%7},{%8,%9},{%0,%1,%2,%3};"
                 : "+f"(c[0]), "+f"(c[1]), "+f"(c[2]), "+f"(c[3])
                 : "r"(a0), "r"(a1), "r"(a2), "r"(a3), "r"(b0), "r"(b1));
}

// Full-width layer: warp's 16 rows x 128 cols. A-fragments af[ks][4] in regs.
template<int KS>
__device__ __forceinline__ void mma_reg(const uint32_t af[][4], const uint4* __restrict__ Wp,
                                        float acc[16][4], int lane){
    #pragma unroll
    for (int nt = 0; nt < 16; nt++){ acc[nt][0]=acc[nt][1]=acc[nt][2]=acc[nt][3]=0.f; }
    #pragma unroll
    for (int ks = 0; ks < KS; ks++){
        #pragma unroll
        for (int ntp = 0; ntp < 8; ntp++){
            uint4 b = Wp[ks * 256 + ntp * 32 + lane];
            mma16(acc[2*ntp],   af[ks][0], af[ks][1], af[ks][2], af[ks][3], b.x, b.y);
            mma16(acc[2*ntp+1], af[ks][0], af[ks][1], af[ks][2], af[ks][3], b.z, b.w);
        }
    }
}

// acc(+bias) -> fast tanh -> repack as next layer's A-fragments (in registers).
__device__ __forceinline__ void transition(const float acc[16][4], uint32_t af[8][4],
                                           const float* __restrict__ bias, int t){
    #pragma unroll
    for (int ks = 0; ks < 8; ks++){
        int c0 = (2*ks) * 8 + 2 * t, c1 = c0 + 8;
        float b00 = bias[c0], b01 = bias[c0 + 1];
        float b10 = bias[c1], b11 = bias[c1 + 1];
        af[ks][0] = pack2(fast_tanh(acc[2*ks][0] + b00),   fast_tanh(acc[2*ks][1] + b01));
        af[ks][1] = pack2(fast_tanh(acc[2*ks][2] + b00),   fast_tanh(acc[2*ks][3] + b01));
        af[ks][2] = pack2(fast_tanh(acc[2*ks+1][0] + b10), fast_tanh(acc[2*ks+1][1] + b11));
        af[ks][3] = pack2(fast_tanh(acc[2*ks+1][2] + b10), fast_tanh(acc[2*ks+1][3] + b11));
    }
}

// Pack W[k][n] (row-major K x 128 fp32) into uint4 B-fragment-pair order.
__device__ __forceinline__ void pack_w4(const float* __restrict__ W, uint4* __restrict__ Wp,
                                        int KS, int K, int tid, int nthr){
    for (int f = tid; f < KS * 8 * 32; f += nthr){
        int ks = f >> 8, ntp = (f >> 5) & 7, lane = f & 31;
        int g = lane >> 2, t = lane & 3;
        int n0 = ntp * 16 + g, n1 = n0 + 8;
        int k0 = ks * 16 + 2 * t, k1 = k0 + 8;
        float a00 = (k0     < K) ? W[(size_t)k0       * 128 + n0] : 0.f;
        float a01 = (k0 + 1 < K) ? W[(size_t)(k0 + 1) * 128 + n0] : 0.f;
        float a10 = (k1     < K) ? W[(size_t)k1       * 128 + n0] : 0.f;
        float a11 = (k1 + 1 < K) ? W[(size_t)(k1 + 1) * 128 + n0] : 0.f;
        float b00 = (k0     < K) ? W[(size_t)k0       * 128 + n1] : 0.f;
        float b01 = (k0 + 1 < K) ? W[(size_t)(k0 + 1) * 128 + n1] : 0.f;
        float b10 = (k1     < K) ? W[(size_t)k1       * 128 + n1] : 0.f;
        float b11 = (k1 + 1 < K) ? W[(size_t)(k1 + 1) * 128 + n1] : 0.f;
        Wp[f] = make_uint4(pack2(a00, a01), pack2(a10, a11), pack2(b00, b01), pack2(b10, b11));
    }
}

// Gather one slab's 16x32 input (row = lane>>1, 16 cols at (lane&1)*16) into
// 8 packed half2 registers. Pure LDG + pack; used for software pipelining.
__device__ __forceinline__ void gather_regs(const float* __restrict__ obs, int slab, int lane,
                                            uint32_t h[8]){
    int r = lane >> 1, q = lane & 1;
    int R = slab * 16 + r;
    const float* sp = obs + (size_t)(R & (BATCHN - 1)) * OBSD;
    const float* np = obs + (size_t)(R >> 3) * OBSD + 18 + (R & 7) * 12;
    #pragma unroll
    for (int jj = 0; jj < 8; jj++){
        int c = q * 16 + 2 * jj;
        float v0 = (c     < 18) ? sp[c]     : ((c     < 30) ? np[c - 18] : 0.f);
        float v1 = (c + 1 < 18) ? sp[c + 1] : ((c + 1 < 30) ? np[c - 17] : 0.f);
        h[jj] = pack2(v0, v1);
    }
}

// smem offsets (fused)
#define F_W1E  0
#define F_W2E  8192
#define F_W1V  40960
#define F_W2V  73728
#define F_BS   106496
#define F_STG  108544
#define F_SMEM 123904   // + 12 warps * 16 rows * 40 halves * 2B

// ============================================================================
// FUSED: gather -> embed MLP -> attn -> value MLP -> combine -> AA.
// Warp owns a 16-row slab (2 batches), all 128 cols; barrier-free main loop.
// Next slab's gather is prefetched into registers and overlapped with the MMAs.
// lane = g*4 + t (g = row-in-8-group / neighbor id, t = k-quarter).
// ============================================================================
__global__ void __launch_bounds__(384, 1)
fused_ev_kernel(const float* __restrict__ obs,
                const float* __restrict__ eW1, const float* __restrict__ eb1,
                const float* __restrict__ eW2, const float* __restrict__ eb2,
                const float* __restrict__ vW1, const float* __restrict__ vb1,
                const float* __restrict__ vW2, const float* __restrict__ vb2,
                float* __restrict__ AA)
{
    extern __shared__ char sm[];
    uint4* W1E = (uint4*)(sm + F_W1E);
    uint4* W2E = (uint4*)(sm + F_W2E);
    uint4* W1V = (uint4*)(sm + F_W1V);
    uint4* W2V = (uint4*)(sm + F_W2V);
    float* bs  = (float*)(sm + F_BS);

    const int tid = threadIdx.x, w = tid >> 5, lane = tid & 31;
    const int g = lane >> 2, t = lane & 3;

    pack_w4(eW1, W1E, 2, 30, tid, 384);
    pack_w4(eW2, W2E, 8, 128, tid, 384);
    pack_w4(vW1, W1V, 8, 128, tid, 384);
    pack_w4(vW2, W2V, 8, 128, tid, 384);
    if (tid < 128){
        bs[tid] = eb1[tid]; bs[128 + tid] = eb2[tid];
        bs[256 + tid] = vb1[tid]; bs[384 + tid] = vb2[tid];
    }
    __syncthreads();

    __half* stg = (__half*)(sm + F_STG) + w * 16 * 40;   // 40-half rows: conflict-free frags
    const float qs = 0.011048543456039806f;              // 1/(8*sqrt(128))
    const int NSLAB = NROWS / 16;                        // 32768
    const int step  = gridDim.x * 12;
    const int rr = lane >> 1, qq = lane & 1;

    uint32_t hg[8];
    int slab0 = blockIdx.x * 12 + w;
    if (slab0 < NSLAB) gather_regs(obs, slab0, lane, hg);

    for (int slab = slab0; slab < NSLAB; slab += step){
        __syncwarp();   // prior iteration's stage reads complete
        *(uint4*)(stg + rr * 40 + qq * 16)     = make_uint4(hg[0], hg[1], hg[2], hg[3]);
        *(uint4*)(stg + rr * 40 + qq * 16 + 8) = make_uint4(hg[4], hg[5], hg[6], hg[7]);
        __syncwarp();

        // ---- embed L1 (K=32): A-frags from stage ----
        uint32_t af1[2][4];
        {
            const __half* s0 = stg + g * 40;
            const __half* s1 = stg + (g + 8) * 40;
            #pragma unroll
            for (int ks = 0; ks < 2; ks++){
                af1[ks][0] = *(const uint32_t*)(s0 + ks * 16 + 2 * t);
                af1[ks][1] = *(const uint32_t*)(s1 + ks * 16 + 2 * t);
                af1[ks][2] = *(const uint32_t*)(s0 + ks * 16 + 2 * t + 8);
                af1[ks][3] = *(const uint32_t*)(s1 + ks * 16 + 2 * t + 8);
            }
        }

        // ---- prefetch next slab's gather (LDG latency hidden by 4 MMA layers) ----
        if (slab + step < NSLAB) gather_regs(obs, slab + step, lane, hg);

        float acc[16][4];
        uint32_t af[8][4];
        mma_reg<2>(af1, W1E, acc, lane);
        transition(acc, af, bs, t);            // h1 -> af
        mma_reg<8>(af, W2E, acc, lane);        // embed L2
        transition(acc, af, bs + 128, t);      // e -> af (fp16, stays in regs)

        // ---- attention weights from e (af) via g-dim shuffles ----
        float wA, wB;
        {
            float fa[32];
            #pragma unroll
            for (int ks = 0; ks < 8; ks++){
                float2 u0 = __half22float2(*(__half2*)&af[ks][0]);
                float2 u2 = __half22float2(*(__half2*)&af[ks][2]);
                fa[4*ks]=u0.x; fa[4*ks+1]=u0.y; fa[4*ks+2]=u2.x; fa[4*ks+3]=u2.y;
            }
            #pragma unroll
            for (int o = 4; o <= 16; o <<= 1)
                #pragma unroll
                for (int i = 0; i < 32; i++) fa[i] += __shfl_xor_sync(0xffffffff, fa[i], o);
            float sA = 0.f;
            #pragma unroll
            for (int ks = 0; ks < 8; ks++){
                float2 u0 = __half22float2(*(__half2*)&af[ks][0]);
                float2 u2 = __half22float2(*(__half2*)&af[ks][2]);
                sA += fa[4*ks]*u0.x + fa[4*ks+1]*u0.y + fa[4*ks+2]*u2.x + fa[4*ks+3]*u2.y;
            }
            sA *= qs;
            sA += __shfl_xor_sync(0xffffffff, sA, 1);
            sA += __shfl_xor_sync(0xffffffff, sA, 2);
            #pragma unroll
            for (int ks = 0; ks < 8; ks++){
                float2 u1 = __half22float2(*(__half2*)&af[ks][1]);
                float2 u3 = __half22float2(*(__half2*)&af[ks][3]);
                fa[4*ks]=u1.x; fa[4*ks+1]=u1.y; fa[4*ks+2]=u3.x; fa[4*ks+3]=u3.y;
            }
            #pragma unroll
            for (int o = 4; o <= 16; o <<= 1)
                #pragma unroll
                for (int i = 0; i < 32; i++) fa[i] += __shfl_xor_sync(0xffffffff, fa[i], o);
            float sB = 0.f;
            #pragma unroll
            for (int ks = 0; ks < 8; ks++){
                float2 u1 = __half22float2(*(__half2*)&af[ks][1]);
                float2 u3 = __half22float2(*(__half2*)&af[ks][3]);
                sB += fa[4*ks]*u1.x + fa[4*ks+1]*u1.y + fa[4*ks+2]*u3.x + fa[4*ks+3]*u3.y;
            }
            sB *= qs;
            sB += __shfl_xor_sync(0xffffffff, sB, 1);
            sB += __shfl_xor_sync(0xffffffff, sB, 2);
            float mxA = sA, mxB = sB;
            #pragma unroll
            for (int o = 4; o <= 16; o <<= 1){
                mxA = fmaxf(mxA, __shfl_xor_sync(0xffffffff, mxA, o));
                mxB = fmaxf(mxB, __shfl_xor_sync(0xffffffff, mxB, o));
            }
            float eA = __expf(sA - mxA), eB = __expf(sB - mxB);
            float uA = eA, uB = eB;
            #pragma unroll
            for (int o = 4; o <= 16; o <<= 1){
                uA += __shfl_xor_sync(0xffffffff, uA, o);
                uB += __shfl_xor_sync(0xffffffff, uB, o);
            }
            wA = __fdividef(eA, uA); wB = __fdividef(eB, uB);
        }

        // ---- value MLP on e ----
        mma_reg<8>(af, W1V, acc, lane);
        transition(acc, af, bs + 256, t);      // h2 -> af
        mma_reg<8>(af, W2V, acc, lane);

        // ---- v = tanh_acc(acc+b2); weighted sum over neighbors (g-dim) -> AA ----
        #pragma unroll
        for (int nt = 0; nt < 16; nt++){
            int c = nt * 8 + 2 * t;
            float b0 = bs[384 + c], b1 = bs[384 + c + 1];
            acc[nt][0] = tanh_acc(acc[nt][0] + b0) * wA;
            acc[nt][1] = tanh_acc(acc[nt][1] + b1) * wA;
            acc[nt][2] = tanh_acc(acc[nt][2] + b0) * wB;
            acc[nt][3] = tanh_acc(acc[nt][3] + b1) * wB;
        }
        #pragma unroll
        for (int o = 4; o <= 16; o <<= 1)
            #pragma unroll
            for (int nt = 0; nt < 16; nt++){
                acc[nt][0] += __shfl_xor_sync(0xffffffff, acc[nt][0], o);
                acc[nt][1] += __shfl_xor_sync(0xffffffff, acc[nt][1], o);
                acc[nt][2] += __shfl_xor_sync(0xffffffff, acc[nt][2], o);
                acc[nt][3] += __shfl_xor_sync(0xffffffff, acc[nt][3], o);
            }
        float* outA = AA + (size_t)(slab * 2) * 128;
        if (lane < 4){
            #pragma unroll
            for (int nt = 0; nt < 16; nt++)
                *(float2*)(outA + nt * 8 + 2 * t) = make_float2(acc[nt][0], acc[nt][1]);
        } else if (lane < 8){
            #pragma unroll
            for (int nt = 0; nt < 16; nt++)
                *(float2*)(outA + 128 + nt * 8 + 2 * t) = make_float2(acc[nt][2], acc[nt][3]);
        }
    }
}

// smem offsets (agent)
#define A_W1   0
#define A_W2   32768
#define A_BS   65536
#define A_SMEM 66560

// ============================================================================
// Agent MLP: AA (fp32) -> tanh(128->128) -> tanh(128->128) -> g_av (fp16)
// Register-chained; A-frags built directly from gmem float2 loads.
// ============================================================================
__global__ void __launch_bounds__(384, 1)
agent_kernel(const float* __restrict__ X,
             const float* __restrict__ W1, const float* __restrict__ b1,
             const float* __restrict__ W2, const float* __restrict__ b2,
             __half* __restrict__ Y)
{
    extern __shared__ char sm[];
    uint4* Wp1 = (uint4*)(sm + A_W1);
    uint4* Wp2 = (uint4*)(sm + A_W2);
    float* bs  = (float*)(sm + A_BS);

    const int tid = threadIdx.x, w = tid >> 5, lane = tid & 31;
    const int g = lane >> 2, t = lane & 3;

    pack_w4(W1, Wp1, 8, 128, tid, 384);
    pack_w4(W2, Wp2, 8, 128, tid, 384);
    if (tid < 128){ bs[tid] = b1[tid]; bs[128 + tid] = b2[tid]; }
    __syncthreads();

    const int NSLAB = BATCHN / 16;            // 4096
    const int step  = gridDim.x * 12;

    for (int slab = blockIdx.x * 12 + w; slab < NSLAB; slab += step){
        const int row0 = slab * 16;
        uint32_t af[8][4];
        {   // A-frags straight from gmem (float2 pairs)
            const float2* pA = (const float2*)(X + (size_t)(row0 + g) * 128);
            const float2* pB = (const float2*)(X + (size_t)(row0 + g + 8) * 128);
            #pragma unroll
            for (int ks = 0; ks < 8; ks++){
                float2 a0 = pA[ks * 8 + t],     b0v = pB[ks * 8 + t];
                float2 a2 = pA[ks * 8 + t + 4], b2v = pB[ks * 8 + t + 4];
                af[ks][0] = pack2(a0.x, a0.y);
                af[ks][1] = pack2(b0v.x, b0v.y);
                af[ks][2] = pack2(a2.x, a2.y);
                af[ks][3] = pack2(b2v.x, b2v.y);
            }
        }
        float acc[16][4];
        mma_reg<8>(af, Wp1, acc, lane);
        transition(acc, af, bs, t);
        mma_reg<8>(af, Wp2, acc, lane);
        {   // output fp16 with accurate tanh
            __half* y0 = Y + (size_t)(row0 + g) * 128;
            __half* y1 = Y + (size_t)(row0 + g + 8) * 128;
            #pragma unroll
            for (int nt = 0; nt < 16; nt++){
                int c = nt * 8 + 2 * t;
                float b0 = bs[128 + c], b1v = bs[128 + c + 1];
                *(__half2*)(y0 + c) = __floats2half2_rn(tanh_acc(acc[nt][0] + b0),
                                                        tanh_acc(acc[nt][1] + b1v));
                *(__half2*)(y1 + c) = __floats2half2_rn(tanh_acc(acc[nt][2] + b0),
                                                        tanh_acc(acc[nt][3] + b1v));
            }
        }
    }
}

// ============================================================================
// Per-group multi-head attention (8 heads x 16 dims over 8 agents) + tile x8.
// ============================================================================
__global__ void __launch_bounds__(128)
mha_kernel(const float* __restrict__ AA, const __half* __restrict__ AV,
           float* __restrict__ out)
{
    __shared__ float ks[8][128];
    __shared__ float vs[8][128];
    const int g = blockIdx.x;
    const int j = threadIdx.x;
    const size_t base = (size_t)g * 8 * 128;

    #pragma unroll
    for (int a = 0; a < 8; a++){
        ks[a][j] = AA[base + a * 128 + j];
        vs[a][j] = __half2float(AV[base + a * 128 + j]);
    }
    __syncthreads();

    float q = 0.0f;
    #pragma unroll
    for (int a = 0; a < 8; a++) q += ks[a][j];
    q *= 0.03125f;                            // mean(1/8) * rsqrt(16)

    float s[8];
    #pragma unroll
    for (int a = 0; a < 8; a++){
        float p = q * ks[a][j];
        p += __shfl_xor_sync(0xffffffff, p, 8);
        p += __shfl_xor_sync(0xffffffff, p, 4);
        p += __shfl_xor_sync(0xffffffff, p, 2);
        p += __shfl_xor_sync(0xffffffff, p, 1);
        s[a] = p;
    }
    float mx = s[0];
    #pragma unroll
    for (int a = 1; a < 8; a++) mx = fmaxf(mx, s[a]);
    float wv[8], wsum = 0.0f;
    #pragma unroll
    for (int a = 0; a < 8; a++){ wv[a] = __expf(s[a] - mx); wsum += wv[a]; }
    const float inv = 1.0f / wsum;

    float o = 0.0f;
    #pragma unroll
    for (int a = 0; a < 8; a++) o += wv[a] * vs[a][j];
    o *= inv;

    #pragma unroll
    for (int tt = 0; tt < 8; tt++)
        out[((size_t)(tt * NGRP + g)) * 128 + j] = o;
}

// ============================================================================
extern "C" void kernel_launch(void* const* d_in, const int* in_sizes, int n_in,
                              void* d_out, int out_size)
{
    const float* obs = (const float*)d_in[0];
    const float* eW1 = (const float*)d_in[1];
    const float* eb1 = (const float*)d_in[2];
    const float* eW2 = (const float*)d_in[3];
    const float* eb2 = (const float*)d_in[4];
    const float* vW1 = (const float*)d_in[5];
    const float* vb1 = (const float*)d_in[6];
    const float* vW2 = (const float*)d_in[7];
    const float* vb2 = (const float*)d_in[8];
    const float* aW1 = (const float*)d_in[9];
    const float* ab1 = (const float*)d_in[10];
    const float* aW2 = (const float*)d_in[11];
    const float* ab2 = (const float*)d_in[12];

    float* out = (float*)d_out;                 // multi_head_attention
    float* AA  = out + (size_t)BATCHN * 128;    // agent_attention

    void* pav; cudaGetSymbolAddress(&pav, g_av);
    __half* av_g = (__half*)pav;

    cudaFuncSetAttribute(fused_ev_kernel, cudaFuncAttributeMaxDynamicSharedMemorySize, F_SMEM);
    cudaFuncSetAttribute(agent_kernel,    cudaFuncAttributeMaxDynamicSharedMemorySize, A_SMEM);

    fused_ev_kernel<<<148, 384, F_SMEM>>>(obs, eW1, eb1, eW2, eb2,
                                          vW1, vb1, vW2, vb2, AA);
    agent_kernel<<<148, 384, A_SMEM>>>(AA, aW1, ab1, aW2, ab2, av_g);
    mha_kernel<<<NGRP, 128>>>(AA, av_g, out);
}

// round 13
// speedup vs baseline: 1.1030x; 1.0060x over previous
#include <cuda_runtime.h>
#include <cuda_fp16.h>
#include <stdint.h>

#define BATCHN 65536
#define NROWS  (BATCHN * 8)
#define NGRP   8192
#define OBSD   114

__device__ __half g_av[(size_t)BATCHN * 128];   // agent values, fp16 (16 MB)

__device__ __forceinline__ float fast_tanh(float x){float y;asm("tanh.approx.f32 %0,%1;":"=f"(y):"f"(x));return y;}
__device__ __forceinline__ float tanh_acc(float x){ return 1.f - __fdividef(2.f, __expf(2.f * x) + 1.f); }
__device__ __forceinline__ uint32_t pack2(float a, float b){ __half2 h = __floats2half2_rn(a, b); return *(uint32_t*)&h; }

__device__ __forceinline__ void mma16(float c[4], uint32_t a0, uint32_t a1, uint32_t a2, uint32_t a3,
                                      uint32_t b0, uint32_t b1){
    asm volatile("mma.sync.aligned.m16n8k16.row.col.f32.f16.f16.f32 "
                 "{%0,%1,%2,%3},{%4,%5,%6,%7},{%8,%9},{%0,%1,%2,%3};"
                 : "+f"(c[0]), "+f"(c[1]), "+f"(c[2]), "+f"(c[3])
                 : "r"(a0), "r"(a1), "r"(a2), "r"(a3), "r"(b0), "r"(b1));
}

// Full-width layer: warp's 16 rows x 128 cols. A-fragments af[ks][4] in regs.
template<int KS>
__device__ __forceinline__ void mma_reg(const uint32_t af[][4], const uint4* __restrict__ Wp,
                                        float acc[16][4], int lane){
    #pragma unroll
    for (int nt = 0; nt < 16; nt++){ acc[nt][0]=acc[nt][1]=acc[nt][2]=acc[nt][3]=0.f; }
    #pragma unroll
    for (int ks = 0; ks < KS; ks++){
        #pragma unroll
        for (int ntp = 0; ntp < 8; ntp++){
            uint4 b = Wp[ks * 256 + ntp * 32 + lane];
            mma16(acc[2*ntp],   af[ks][0], af[ks][1], af[ks][2], af[ks][3], b.x, b.y);
            mma16(acc[2*ntp+1], af[ks][0], af[ks][1], af[ks][2], af[ks][3], b.z, b.w);
        }
    }
}

// acc(+bias) -> fast tanh -> repack as next layer's A-fragments (in registers).
__device__ __forceinline__ void transition(const float acc[16][4], uint32_t af[8][4],
                                           const float* __restrict__ bias, int t){
    #pragma unroll
    for (int ks = 0; ks < 8; ks++){
        int c0 = (2*ks) * 8 + 2 * t, c1 = c0 + 8;
        float b00 = bias[c0], b01 = bias[c0 + 1];
        float b10 = bias[c1], b11 = bias[c1 + 1];
        af[ks][0] = pack2(fast_tanh(acc[2*ks][0] + b00),   fast_tanh(acc[2*ks][1] + b01));
        af[ks][1] = pack2(fast_tanh(acc[2*ks][2] + b00),   fast_tanh(acc[2*ks][3] + b01));
        af[ks][2] = pack2(fast_tanh(acc[2*ks+1][0] + b10), fast_tanh(acc[2*ks+1][1] + b11));
        af[ks][3] = pack2(fast_tanh(acc[2*ks+1][2] + b10), fast_tanh(acc[2*ks+1][3] + b11));
    }
}

// Pack W[k][n] (row-major K x 128 fp32) into uint4 B-fragment-pair order.
__device__ __forceinline__ void pack_w4(const float* __restrict__ W, uint4* __restrict__ Wp,
                                        int KS, int K, int tid, int nthr){
    for (int f = tid; f < KS * 8 * 32; f += nthr){
        int ks = f >> 8, ntp = (f >> 5) & 7, lane = f & 31;
        int g = lane >> 2, t = lane & 3;
        int n0 = ntp * 16 + g, n1 = n0 + 8;
        int k0 = ks * 16 + 2 * t, k1 = k0 + 8;
        float a00 = (k0     < K) ? W[(size_t)k0       * 128 + n0] : 0.f;
        float a01 = (k0 + 1 < K) ? W[(size_t)(k0 + 1) * 128 + n0] : 0.f;
        float a10 = (k1     < K) ? W[(size_t)k1       * 128 + n0] : 0.f;
        float a11 = (k1 + 1 < K) ? W[(size_t)(k1 + 1) * 128 + n0] : 0.f;
        float b00 = (k0     < K) ? W[(size_t)k0       * 128 + n1] : 0.f;
        float b01 = (k0 + 1 < K) ? W[(size_t)(k0 + 1) * 128 + n1] : 0.f;
        float b10 = (k1     < K) ? W[(size_t)k1       * 128 + n1] : 0.f;
        float b11 = (k1 + 1 < K) ? W[(size_t)(k1 + 1) * 128 + n1] : 0.f;
        Wp[f] = make_uint4(pack2(a00, a01), pack2(a10, a11), pack2(b00, b01), pack2(b10, b11));
    }
}

// ---- Coalesced gather prefetch ----
// self: 288 floats, linear i = k*32+lane -> obs[(slab*16 + i/18) & 65535][i%18]
// nbr : 192 floats, linear i = k*32+lane -> obs[slab*2 + i/96][18 + i%96]
// Packed into 5 + 3 uint32 (half2 pairs over k).
__device__ __forceinline__ void gather_pf(const float* __restrict__ obs, int slab, int lane,
                                          uint32_t ps[5], uint32_t pn[3]){
    const int base = slab * 16;
    #pragma unroll
    for (int k = 0; k < 4; k++){
        int i0 = (2*k) * 32 + lane, i1 = i0 + 32;
        float v0 = obs[(size_t)((base + i0 / 18) & (BATCHN - 1)) * OBSD + i0 % 18];
        float v1 = obs[(size_t)((base + i1 / 18) & (BATCHN - 1)) * OBSD + i1 % 18];
        ps[k] = pack2(v0, v1);
    }
    {
        int i0 = 8 * 32 + lane;
        float v0 = obs[(size_t)((base + i0 / 18) & (BATCHN - 1)) * OBSD + i0 % 18];
        ps[4] = pack2(v0, 0.f);
    }
    const float* nb = obs + (size_t)(slab * 2) * OBSD + 18;
    #pragma unroll
    for (int k = 0; k < 3; k++){
        int i0 = (2*k) * 32 + lane, i1 = i0 + 32;
        float v0 = (i0 < 96) ? nb[i0] : nb[OBSD + (i0 - 96)];
        float v1 = (i1 < 96) ? nb[i1] : nb[OBSD + (i1 - 96)];
        pn[k] = pack2(v0, v1);
    }
}

// Store prefetched values into the 16x40-half stage (scattered STS.16).
__device__ __forceinline__ void stage_store(__half* __restrict__ stg, int lane,
                                            const uint32_t ps[5], const uint32_t pn[3]){
    #pragma unroll
    for (int k = 0; k < 5; k++){
        int i0 = (2*k) * 32 + lane;
        stg[(i0 / 18) * 40 + (i0 % 18)] = __ushort_as_half((unsigned short)(ps[k] & 0xffffu));
        if (k < 4){
            int i1 = i0 + 32;
            stg[(i1 / 18) * 40 + (i1 % 18)] = __ushort_as_half((unsigned short)(ps[k] >> 16));
        }
    }
    #pragma unroll
    for (int k = 0; k < 3; k++){
        int i0 = (2*k) * 32 + lane, i1 = i0 + 32;
        int r0 = (i0 / 96) * 8 + (i0 / 12) % 8, c0 = 18 + i0 % 12;
        int r1 = (i1 / 96) * 8 + (i1 / 12) % 8, c1 = 18 + i1 % 12;
        stg[r0 * 40 + c0] = __ushort_as_half((unsigned short)(pn[k] & 0xffffu));
        stg[r1 * 40 + c1] = __ushort_as_half((unsigned short)(pn[k] >> 16));
    }
}

// smem offsets (fused)
#define F_W1E  0
#define F_W2E  8192
#define F_W1V  40960
#define F_W2V  73728
#define F_BS   106496
#define F_STG  108544
#define F_SMEM (108544 + 14 * 16 * 40 * 2)   // 126464

// ============================================================================
// FUSED: gather -> embed MLP -> attn -> value MLP -> combine -> AA.
// 448 threads (14 warps); warp owns a 16-row slab; barrier-free main loop.
// ============================================================================
__global__ void __launch_bounds__(448, 1)
fused_ev_kernel(const float* __restrict__ obs,
                const float* __restrict__ eW1, const float* __restrict__ eb1,
                const float* __restrict__ eW2, const float* __restrict__ eb2,
                const float* __restrict__ vW1, const float* __restrict__ vb1,
                const float* __restrict__ vW2, const float* __restrict__ vb2,
                float* __restrict__ AA)
{
    extern __shared__ char sm[];
    uint4* W1E = (uint4*)(sm + F_W1E);
    uint4* W2E = (uint4*)(sm + F_W2E);
    uint4* W1V = (uint4*)(sm + F_W1V);
    uint4* W2V = (uint4*)(sm + F_W2V);
    float* bs  = (float*)(sm + F_BS);

    const int tid = threadIdx.x, w = tid >> 5, lane = tid & 31;
    const int g = lane >> 2, t = lane & 3;

    pack_w4(eW1, W1E, 2, 30, tid, 448);
    pack_w4(eW2, W2E, 8, 128, tid, 448);
    pack_w4(vW1, W1V, 8, 128, tid, 448);
    pack_w4(vW2, W2V, 8, 128, tid, 448);
    if (tid < 128){
        bs[tid] = eb1[tid]; bs[128 + tid] = eb2[tid];
        bs[256 + tid] = vb1[tid]; bs[384 + tid] = vb2[tid];
    }
    __syncthreads();

    __half* stg = (__half*)(sm + F_STG) + w * 16 * 40;
    const float qs = 0.011048543456039806f;   // 1/(8*sqrt(128))
    const int NSLAB = NROWS / 16;             // 32768
    const int step  = gridDim.x * 14;

    // zero pad cols 30,31 once (never overwritten; frag cols 30,31 read them)
    if (lane < 16) *(uint32_t*)(stg + lane * 40 + 30) = 0u;
    __syncwarp();

    uint32_t ps[5], pn[3];
    int slab0 = blockIdx.x * 14 + w;
    if (slab0 < NSLAB) gather_pf(obs, slab0, lane, ps, pn);

    for (int slab = slab0; slab < NSLAB; slab += step){
        __syncwarp();   // prior iteration's stage reads complete
        stage_store(stg, lane, ps, pn);
        __syncwarp();

        // ---- embed L1 (K=32): A-frags from stage ----
        uint32_t af1[2][4];
        {
            const __half* s0 = stg + g * 40;
            const __half* s1 = stg + (g + 8) * 40;
            #pragma unroll
            for (int ks = 0; ks < 2; ks++){
                af1[ks][0] = *(const uint32_t*)(s0 + ks * 16 + 2 * t);
                af1[ks][1] = *(const uint32_t*)(s1 + ks * 16 + 2 * t);
                af1[ks][2] = *(const uint32_t*)(s0 + ks * 16 + 2 * t + 8);
                af1[ks][3] = *(const uint32_t*)(s1 + ks * 16 + 2 * t + 8);
            }
        }

        // ---- prefetch next slab (LDG latency hidden by 4 MMA layers) ----
        if (slab + step < NSLAB) gather_pf(obs, slab + step, lane, ps, pn);

        float acc[16][4];
        uint32_t af[8][4];
        mma_reg<2>(af1, W1E, acc, lane);
        transition(acc, af, bs, t);            // h1 -> af
        mma_reg<8>(af, W2E, acc, lane);        // embed L2
        transition(acc, af, bs + 128, t);      // e -> af (fp16, stays in regs)

        // ---- attention weights from e: chunked g-dim reduction (low reg pressure) ----
        float wA, wB;
        {
            float sA = 0.f, sB = 0.f;
            #pragma unroll
            for (int c = 0; c < 4; c++){
                float oa[8], fb[8];
                {   // batch A values for ks pair {2c, 2c+1}
                    float2 u0 = __half22float2(*(__half2*)&af[2*c][0]);
                    float2 u2 = __half22float2(*(__half2*)&af[2*c][2]);
                    float2 u4 = __half22float2(*(__half2*)&af[2*c+1][0]);
                    float2 u6 = __half22float2(*(__half2*)&af[2*c+1][2]);
                    oa[0]=u0.x; oa[1]=u0.y; oa[2]=u2.x; oa[3]=u2.y;
                    oa[4]=u4.x; oa[5]=u4.y; oa[6]=u6.x; oa[7]=u6.y;
                }
                #pragma unroll
                for (int i = 0; i < 8; i++) fb[i] = oa[i];
                #pragma unroll
                for (int o = 4; o <= 16; o <<= 1)
                    #pragma unroll
                    for (int i = 0; i < 8; i++) fb[i] += __shfl_xor_sync(0xffffffff, fb[i], o);
                #pragma unroll
                for (int i = 0; i < 8; i++) sA = fmaf(fb[i], oa[i], sA);
                {   // batch B
                    float2 u1 = __half22float2(*(__half2*)&af[2*c][1]);
                    float2 u3 = __half22float2(*(__half2*)&af[2*c][3]);
                    float2 u5 = __half22float2(*(__half2*)&af[2*c+1][1]);
                    float2 u7 = __half22float2(*(__half2*)&af[2*c+1][3]);
                    oa[0]=u1.x; oa[1]=u1.y; oa[2]=u3.x; oa[3]=u3.y;
                    oa[4]=u5.x; oa[5]=u5.y; oa[6]=u7.x; oa[7]=u7.y;
                }
                #pragma unroll
                for (int i = 0; i < 8; i++) fb[i] = oa[i];
                #pragma unroll
                for (int o = 4; o <= 16; o <<= 1)
                    #pragma unroll
                    for (int i = 0; i < 8; i++) fb[i] += __shfl_xor_sync(0xffffffff, fb[i], o);
                #pragma unroll
                for (int i = 0; i < 8; i++) sB = fmaf(fb[i], oa[i], sB);
            }
            sA *= qs; sB *= qs;
            sA += __shfl_xor_sync(0xffffffff, sA, 1);
            sA += __shfl_xor_sync(0xffffffff, sA, 2);
            sB += __shfl_xor_sync(0xffffffff, sB, 1);
            sB += __shfl_xor_sync(0xffffffff, sB, 2);
            float mxA = sA, mxB = sB;
            #pragma unroll
            for (int o = 4; o <= 16; o <<= 1){
                mxA = fmaxf(mxA, __shfl_xor_sync(0xffffffff, mxA, o));
                mxB = fmaxf(mxB, __shfl_xor_sync(0xffffffff, mxB, o));
            }
            float eA = __expf(sA - mxA), eB = __expf(sB - mxB);
            float uA = eA, uB = eB;
            #pragma unroll
            for (int o = 4; o <= 16; o <<= 1){
                uA += __shfl_xor_sync(0xffffffff, uA, o);
                uB += __shfl_xor_sync(0xffffffff, uB, o);
            }
            wA = __fdividef(eA, uA); wB = __fdividef(eB, uB);
        }

        // ---- value MLP on e ----
        mma_reg<8>(af, W1V, acc, lane);
        transition(acc, af, bs + 256, t);      // h2 -> af
        mma_reg<8>(af, W2V, acc, lane);

        // ---- v = tanh_acc(acc+b2); weighted sum over neighbors (g-dim) -> AA ----
        #pragma unroll
        for (int nt = 0; nt < 16; nt++){
            int c = nt * 8 + 2 * t;
            float b0 = bs[384 + c], b1 = bs[384 + c + 1];
            acc[nt][0] = tanh_acc(acc[nt][0] + b0) * wA;
            acc[nt][1] = tanh_acc(acc[nt][1] + b1) * wA;
            acc[nt][2] = tanh_acc(acc[nt][2] + b0) * wB;
            acc[nt][3] = tanh_acc(acc[nt][3] + b1) * wB;
        }
        #pragma unroll
        for (int o = 4; o <= 16; o <<= 1)
            #pragma unroll
            for (int nt = 0; nt < 16; nt++){
                acc[nt][0] += __shfl_xor_sync(0xffffffff, acc[nt][0], o);
                acc[nt][1] += __shfl_xor_sync(0xffffffff, acc[nt][1], o);
                acc[nt][2] += __shfl_xor_sync(0xffffffff, acc[nt][2], o);
                acc[nt][3] += __shfl_xor_sync(0xffffffff, acc[nt][3], o);
            }
        float* outA = AA + (size_t)(slab * 2) * 128;
        if (lane < 4){
            #pragma unroll
            for (int nt = 0; nt < 16; nt++)
                *(float2*)(outA + nt * 8 + 2 * t) = make_float2(acc[nt][0], acc[nt][1]);
        } else if (lane < 8){
            #pragma unroll
            for (int nt = 0; nt < 16; nt++)
                *(float2*)(outA + 128 + nt * 8 + 2 * t) = make_float2(acc[nt][2], acc[nt][3]);
        }
    }
}

// smem offsets (agent)
#define A_W1   0
#define A_W2   32768
#define A_BS   65536
#define A_SMEM 66560

// ============================================================================
// Agent MLP: AA (fp32) -> tanh(128->128) -> tanh(128->128) -> g_av (fp16)
// ============================================================================
__global__ void __launch_bounds__(448, 1)
agent_kernel(const float* __restrict__ X,
             const float* __restrict__ W1, const float* __restrict__ b1,
             const float* __restrict__ W2, const float* __restrict__ b2,
             __half* __restrict__ Y)
{
    extern __shared__ char sm[];
    uint4* Wp1 = (uint4*)(sm + A_W1);
    uint4* Wp2 = (uint4*)(sm + A_W2);
    float* bs  = (float*)(sm + A_BS);

    const int tid = threadIdx.x, w = tid >> 5, lane = tid & 31;
    const int g = lane >> 2, t = lane & 3;

    pack_w4(W1, Wp1, 8, 128, tid, 448);
    pack_w4(W2, Wp2, 8, 128, tid, 448);
    if (tid < 128){ bs[tid] = b1[tid]; bs[128 + tid] = b2[tid]; }
    __syncthreads();

    const int NSLAB = BATCHN / 16;            // 4096
    const int step  = gridDim.x * 14;

    for (int slab = blockIdx.x * 14 + w; slab < NSLAB; slab += step){
        const int row0 = slab * 16;
        uint32_t af[8][4];
        {
            const float2* pA = (const float2*)(X + (size_t)(row0 + g) * 128);
            const float2* pB = (const float2*)(X + (size_t)(row0 + g + 8) * 128);
            #pragma unroll
            for (int ks = 0; ks < 8; ks++){
                float2 a0 = pA[ks * 8 + t],     b0v = pB[ks * 8 + t];
                float2 a2 = pA[ks * 8 + t + 4], b2v = pB[ks * 8 + t + 4];
                af[ks][0] = pack2(a0.x, a0.y);
                af[ks][1] = pack2(b0v.x, b0v.y);
                af[ks][2] = pack2(a2.x, a2.y);
                af[ks][3] = pack2(b2v.x, b2v.y);
            }
        }
        float acc[16][4];
        mma_reg<8>(af, Wp1, acc, lane);
        transition(acc, af, bs, t);
        mma_reg<8>(af, Wp2, acc, lane);
        {
            __half* y0 = Y + (size_t)(row0 + g) * 128;
            __half* y1 = Y + (size_t)(row0 + g + 8) * 128;
            #pragma unroll
            for (int nt = 0; nt < 16; nt++){
                int c = nt * 8 + 2 * t;
                float b0 = bs[128 + c], b1v = bs[128 + c + 1];
                *(__half2*)(y0 + c) = __floats2half2_rn(tanh_acc(acc[nt][0] + b0),
                                                        tanh_acc(acc[nt][1] + b1v));
                *(__half2*)(y1 + c) = __floats2half2_rn(tanh_acc(acc[nt][2] + b0),
                                                        tanh_acc(acc[nt][3] + b1v));
            }
        }
    }
}

// ============================================================================
// Per-group multi-head attention (8 heads x 16 dims over 8 agents) + tile x8.
// ============================================================================
__global__ void __launch_bounds__(128)
mha_kernel(const float* __restrict__ AA, const __half* __restrict__ AV,
           float* __restrict__ out)
{
    __shared__ float ks[8][128];
    __shared__ float vs[8][128];
    const int g = blockIdx.x;
    const int j = threadIdx.x;
    const size_t base = (size_t)g * 8 * 128;

    #pragma unroll
    for (int a = 0; a < 8; a++){
        ks[a][j] = AA[base + a * 128 + j];
        vs[a][j] = __half2float(AV[base + a * 128 + j]);
    }
    __syncthreads();

    float q = 0.0f;
    #pragma unroll
    for (int a = 0; a < 8; a++) q += ks[a][j];
    q *= 0.03125f;                            // mean(1/8) * rsqrt(16)

    float s[8];
    #pragma unroll
    for (int a = 0; a < 8; a++){
        float p = q * ks[a][j];
        p += __shfl_xor_sync(0xffffffff, p, 8);
        p += __shfl_xor_sync(0xffffffff, p, 4);
        p += __shfl_xor_sync(0xffffffff, p, 2);
        p += __shfl_xor_sync(0xffffffff, p, 1);
        s[a] = p;
    }
    float mx = s[0];
    #pragma unroll
    for (int a = 1; a < 8; a++) mx = fmaxf(mx, s[a]);
    float wv[8], wsum = 0.0f;
    #pragma unroll
    for (int a = 0; a < 8; a++){ wv[a] = __expf(s[a] - mx); wsum += wv[a]; }
    const float inv = 1.0f / wsum;

    float o = 0.0f;
    #pragma unroll
    for (int a = 0; a < 8; a++) o += wv[a] * vs[a][j];
    o *= inv;

    #pragma unroll
    for (int tt = 0; tt < 8; tt++)
        out[((size_t)(tt * NGRP + g)) * 128 + j] = o;
}

// ============================================================================
extern "C" void kernel_launch(void* const* d_in, const int* in_sizes, int n_in,
                              void* d_out, int out_size)
{
    const float* obs = (const float*)d_in[0];
    const float* eW1 = (const float*)d_in[1];
    const float* eb1 = (const float*)d_in[2];
    const float* eW2 = (const float*)d_in[3];
    const float* eb2 = (const float*)d_in[4];
    const float* vW1 = (const float*)d_in[5];
    const float* vb1 = (const float*)d_in[6];
    const float* vW2 = (const float*)d_in[7];
    const float* vb2 = (const float*)d_in[8];
    const float* aW1 = (const float*)d_in[9];
    const float* ab1 = (const float*)d_in[10];
    const float* aW2 = (const float*)d_in[11];
    const float* ab2 = (const float*)d_in[12];

    float* out = (float*)d_out;                 // multi_head_attention
    float* AA  = out + (size_t)BATCHN * 128;    // agent_attention

    void* pav; cudaGetSymbolAddress(&pav, g_av);
    __half* av_g = (__half*)pav;

    cudaFuncSetAttribute(fused_ev_kernel, cudaFuncAttributeMaxDynamicSharedMemorySize, F_SMEM);
    cudaFuncSetAttribute(agent_kernel,    cudaFuncAttributeMaxDynamicSharedMemorySize, A_SMEM);

    fused_ev_kernel<<<148, 448, F_SMEM>>>(obs, eW1, eb1, eW2, eb2,
                                          vW1, vb1, vW2, vb2, AA);
    agent_kernel<<<148, 448, A_SMEM>>>(AA, aW1, ab1, aW2, ab2, av_g);
    mha_kernel<<<NGRP, 128>>>(AA, av_g, out);
}

// round 14
// speedup vs baseline: 1.1839x; 1.0734x over previous
#include <cuda_runtime.h>
#include <cuda_fp16.h>
#include <stdint.h>

#define BATCHN 65536
#define NROWS  (BATCHN * 8)
#define NGRP   8192
#define OBSD   114

__device__ __half g_av[(size_t)BATCHN * 128];   // agent values, fp16 (16 MB)

__device__ __forceinline__ float fast_tanh(float x){float y;asm("tanh.approx.f32 %0,%1;":"=f"(y):"f"(x));return y;}
__device__ __forceinline__ float tanh_acc(float x){ return 1.f - __fdividef(2.f, __expf(2.f * x) + 1.f); }
__device__ __forceinline__ uint32_t pack2(float a, float b){ __half2 h = __floats2half2_rn(a, b); return *(uint32_t*)&h; }

__device__ __forceinline__ void mma16(float c[4], uint32_t a0, uint32_t a1, uint32_t a2, uint32_t a3,
                                      uint32_t b0, uint32_t b1){
    asm volatile("mma.sync.aligned.m16n8k16.row.col.f32.f16.f16.f32 "
                 "{%0,%1,%2,%3},{%4,%5,%6,%7},{%8,%9},{%0,%1,%2,%3};"
                 : "+f"(c[0]), "+f"(c[1]), "+f"(c[2]), "+f"(c[3])
                 : "r"(a0), "r"(a1), "r"(a2), "r"(a3), "r"(b0), "r"(b1));
}

// Full-width layer: warp's 16 rows x 128 cols. A-fragments af[ks][4] in regs.
template<int KS>
__device__ __forceinline__ void mma_reg(const uint32_t af[][4], const uint4* __restrict__ Wp,
                                        float acc[16][4], int lane){
    #pragma unroll
    for (int nt = 0; nt < 16; nt++){ acc[nt][0]=acc[nt][1]=acc[nt][2]=acc[nt][3]=0.f; }
    #pragma unroll
    for (int ks = 0; ks < KS; ks++){
        #pragma unroll
        for (int ntp = 0; ntp < 8; ntp++){
            uint4 b = Wp[ks * 256 + ntp * 32 + lane];
            mma16(acc[2*ntp],   af[ks][0], af[ks][1], af[ks][2], af[ks][3], b.x, b.y);
            mma16(acc[2*ntp+1], af[ks][0], af[ks][1], af[ks][2], af[ks][3], b.z, b.w);
        }
    }
}

// acc(+bias) -> fast tanh -> repack as next layer's A-fragments (in registers).
__device__ __forceinline__ void transition(const float acc[16][4], uint32_t af[8][4],
                                           const float* __restrict__ bias, int t){
    #pragma unroll
    for (int ks = 0; ks < 8; ks++){
        int c0 = (2*ks) * 8 + 2 * t, c1 = c0 + 8;
        float b00 = bias[c0], b01 = bias[c0 + 1];
        float b10 = bias[c1], b11 = bias[c1 + 1];
        af[ks][0] = pack2(fast_tanh(acc[2*ks][0] + b00),   fast_tanh(acc[2*ks][1] + b01));
        af[ks][1] = pack2(fast_tanh(acc[2*ks][2] + b00),   fast_tanh(acc[2*ks][3] + b01));
        af[ks][2] = pack2(fast_tanh(acc[2*ks+1][0] + b10), fast_tanh(acc[2*ks+1][1] + b11));
        af[ks][3] = pack2(fast_tanh(acc[2*ks+1][2] + b10), fast_tanh(acc[2*ks+1][3] + b11));
    }
}

// Pack W[k][n] (row-major K x 128 fp32) into uint4 B-fragment-pair order.
__device__ __forceinline__ void pack_w4(const float* __restrict__ W, uint4* __restrict__ Wp,
                                        int KS, int K, int tid, int nthr){
    for (int f = tid; f < KS * 8 * 32; f += nthr){
        int ks = f >> 8, ntp = (f >> 5) & 7, lane = f & 31;
        int g = lane >> 2, t = lane & 3;
        int n0 = ntp * 16 + g, n1 = n0 + 8;
        int k0 = ks * 16 + 2 * t, k1 = k0 + 8;
        float a00 = (k0     < K) ? W[(size_t)k0       * 128 + n0] : 0.f;
        float a01 = (k0 + 1 < K) ? W[(size_t)(k0 + 1) * 128 + n0] : 0.f;
        float a10 = (k1     < K) ? W[(size_t)k1       * 128 + n0] : 0.f;
        float a11 = (k1 + 1 < K) ? W[(size_t)(k1 + 1) * 128 + n0] : 0.f;
        float b00 = (k0     < K) ? W[(size_t)k0       * 128 + n1] : 0.f;
        float b01 = (k0 + 1 < K) ? W[(size_t)(k0 + 1) * 128 + n1] : 0.f;
        float b10 = (k1     < K) ? W[(size_t)k1       * 128 + n1] : 0.f;
        float b11 = (k1 + 1 < K) ? W[(size_t)(k1 + 1) * 128 + n1] : 0.f;
        Wp[f] = make_uint4(pack2(a00, a01), pack2(a10, a11), pack2(b00, b01), pack2(b10, b11));
    }
}

// ---- Coalesced gather prefetch ----
__device__ __forceinline__ void gather_pf(const float* __restrict__ obs, int slab, int lane,
                                          uint32_t ps[5], uint32_t pn[3]){
    const int base = slab * 16;
    #pragma unroll
    for (int k = 0; k < 4; k++){
        int i0 = (2*k) * 32 + lane, i1 = i0 + 32;
        float v0 = obs[(size_t)((base + i0 / 18) & (BATCHN - 1)) * OBSD + i0 % 18];
        float v1 = obs[(size_t)((base + i1 / 18) & (BATCHN - 1)) * OBSD + i1 % 18];
        ps[k] = pack2(v0, v1);
    }
    {
        int i0 = 8 * 32 + lane;
        float v0 = obs[(size_t)((base + i0 / 18) & (BATCHN - 1)) * OBSD + i0 % 18];
        ps[4] = pack2(v0, 0.f);
    }
    const float* nb = obs + (size_t)(slab * 2) * OBSD + 18;
    #pragma unroll
    for (int k = 0; k < 3; k++){
        int i0 = (2*k) * 32 + lane, i1 = i0 + 32;
        float v0 = (i0 < 96) ? nb[i0] : nb[OBSD + (i0 - 96)];
        float v1 = (i1 < 96) ? nb[i1] : nb[OBSD + (i1 - 96)];
        pn[k] = pack2(v0, v1);
    }
}

// Store prefetched values into the 16x40-half stage (scattered STS.16).
__device__ __forceinline__ void stage_store(__half* __restrict__ stg, int lane,
                                            const uint32_t ps[5], const uint32_t pn[3]){
    #pragma unroll
    for (int k = 0; k < 5; k++){
        int i0 = (2*k) * 32 + lane;
        stg[(i0 / 18) * 40 + (i0 % 18)] = __ushort_as_half((unsigned short)(ps[k] & 0xffffu));
        if (k < 4){
            int i1 = i0 + 32;
            stg[(i1 / 18) * 40 + (i1 % 18)] = __ushort_as_half((unsigned short)(ps[k] >> 16));
        }
    }
    #pragma unroll
    for (int k = 0; k < 3; k++){
        int i0 = (2*k) * 32 + lane, i1 = i0 + 32;
        int r0 = (i0 / 96) * 8 + (i0 / 12) % 8, c0 = 18 + i0 % 12;
        int r1 = (i1 / 96) * 8 + (i1 / 12) % 8, c1 = 18 + i1 % 12;
        stg[r0 * 40 + c0] = __ushort_as_half((unsigned short)(pn[k] & 0xffffu));
        stg[r1 * 40 + c1] = __ushort_as_half((unsigned short)(pn[k] >> 16));
    }
}

// smem offsets (fused)
#define F_W1E  0
#define F_W2E  8192
#define F_W1V  40960
#define F_W2V  73728
#define F_BS   106496
#define F_STG  108544
#define F_SMEM (108544 + 16 * 16 * 40 * 2)   // 129024

// ============================================================================
// FUSED: gather -> embed MLP -> attn -> value MLP -> combine -> AA.
// 512 threads (16 warps, 4/SMSP, RF exactly full at 128 regs).
// ============================================================================
__global__ void __launch_bounds__(512, 1)
fused_ev_kernel(const float* __restrict__ obs,
                const float* __restrict__ eW1, const float* __restrict__ eb1,
                const float* __restrict__ eW2, const float* __restrict__ eb2,
                const float* __restrict__ vW1, const float* __restrict__ vb1,
                const float* __restrict__ vW2, const float* __restrict__ vb2,
                float* __restrict__ AA)
{
    extern __shared__ char sm[];
    uint4* W1E = (uint4*)(sm + F_W1E);
    uint4* W2E = (uint4*)(sm + F_W2E);
    uint4* W1V = (uint4*)(sm + F_W1V);
    uint4* W2V = (uint4*)(sm + F_W2V);
    float* bs  = (float*)(sm + F_BS);

    const int tid = threadIdx.x, w = tid >> 5, lane = tid & 31;
    const int g = lane >> 2, t = lane & 3;

    pack_w4(eW1, W1E, 2, 30, tid, 512);
    pack_w4(eW2, W2E, 8, 128, tid, 512);
    pack_w4(vW1, W1V, 8, 128, tid, 512);
    pack_w4(vW2, W2V, 8, 128, tid, 512);
    if (tid < 128){
        bs[tid] = eb1[tid]; bs[128 + tid] = eb2[tid];
        bs[256 + tid] = vb1[tid]; bs[384 + tid] = vb2[tid];
    }
    __syncthreads();

    __half* stg = (__half*)(sm + F_STG) + w * 16 * 40;
    const float qs = 0.011048543456039806f;   // 1/(8*sqrt(128))
    const int NSLAB = NROWS / 16;             // 32768
    const int step  = gridDim.x * 16;

    // zero pad cols 30,31 once (never overwritten; frag cols 30,31 read them)
    if (lane < 16) *(uint32_t*)(stg + lane * 40 + 30) = 0u;
    __syncwarp();

    uint32_t ps[5], pn[3];
    int slab0 = blockIdx.x * 16 + w;
    if (slab0 < NSLAB) gather_pf(obs, slab0, lane, ps, pn);

    for (int slab = slab0; slab < NSLAB; slab += step){
        __syncwarp();   // prior iteration's stage reads complete
        stage_store(stg, lane, ps, pn);
        __syncwarp();

        // ---- embed L1 (K=32): A-frags from stage ----
        uint32_t af1[2][4];
        {
            const __half* s0 = stg + g * 40;
            const __half* s1 = stg + (g + 8) * 40;
            #pragma unroll
            for (int ks = 0; ks < 2; ks++){
                af1[ks][0] = *(const uint32_t*)(s0 + ks * 16 + 2 * t);
                af1[ks][1] = *(const uint32_t*)(s1 + ks * 16 + 2 * t);
                af1[ks][2] = *(const uint32_t*)(s0 + ks * 16 + 2 * t + 8);
                af1[ks][3] = *(const uint32_t*)(s1 + ks * 16 + 2 * t + 8);
            }
        }

        // ---- prefetch next slab (LDG latency hidden by 4 MMA layers) ----
        if (slab + step < NSLAB) gather_pf(obs, slab + step, lane, ps, pn);

        float acc[16][4];
        uint32_t af[8][4];
        mma_reg<2>(af1, W1E, acc, lane);
        transition(acc, af, bs, t);            // h1 -> af
        mma_reg<8>(af, W2E, acc, lane);        // embed L2
        transition(acc, af, bs + 128, t);      // e -> af (fp16, stays in regs)

        // ---- attention weights from e: chunked g-dim reduction ----
        float wA, wB;
        {
            float sA = 0.f, sB = 0.f;
            #pragma unroll
            for (int c = 0; c < 4; c++){
                float oa[8], fb[8];
                {
                    float2 u0 = __half22float2(*(__half2*)&af[2*c][0]);
                    float2 u2 = __half22float2(*(__half2*)&af[2*c][2]);
                    float2 u4 = __half22float2(*(__half2*)&af[2*c+1][0]);
                    float2 u6 = __half22float2(*(__half2*)&af[2*c+1][2]);
                    oa[0]=u0.x; oa[1]=u0.y; oa[2]=u2.x; oa[3]=u2.y;
                    oa[4]=u4.x; oa[5]=u4.y; oa[6]=u6.x; oa[7]=u6.y;
                }
                #pragma unroll
                for (int i = 0; i < 8; i++) fb[i] = oa[i];
                #pragma unroll
                for (int o = 4; o <= 16; o <<= 1)
                    #pragma unroll
                    for (int i = 0; i < 8; i++) fb[i] += __shfl_xor_sync(0xffffffff, fb[i], o);
                #pragma unroll
                for (int i = 0; i < 8; i++) sA = fmaf(fb[i], oa[i], sA);
                {
                    float2 u1 = __half22float2(*(__half2*)&af[2*c][1]);
                    float2 u3 = __half22float2(*(__half2*)&af[2*c][3]);
                    float2 u5 = __half22float2(*(__half2*)&af[2*c+1][1]);
                    float2 u7 = __half22float2(*(__half2*)&af[2*c+1][3]);
                    oa[0]=u1.x; oa[1]=u1.y; oa[2]=u3.x; oa[3]=u3.y;
                    oa[4]=u5.x; oa[5]=u5.y; oa[6]=u7.x; oa[7]=u7.y;
                }
                #pragma unroll
                for (int i = 0; i < 8; i++) fb[i] = oa[i];
                #pragma unroll
                for (int o = 4; o <= 16; o <<= 1)
                    #pragma unroll
                    for (int i = 0; i < 8; i++) fb[i] += __shfl_xor_sync(0xffffffff, fb[i], o);
                #pragma unroll
                for (int i = 0; i < 8; i++) sB = fmaf(fb[i], oa[i], sB);
            }
            sA *= qs; sB *= qs;
            sA += __shfl_xor_sync(0xffffffff, sA, 1);
            sA += __shfl_xor_sync(0xffffffff, sA, 2);
            sB += __shfl_xor_sync(0xffffffff, sB, 1);
            sB += __shfl_xor_sync(0xffffffff, sB, 2);
            float mxA = sA, mxB = sB;
            #pragma unroll
            for (int o = 4; o <= 16; o <<= 1){
                mxA = fmaxf(mxA, __shfl_xor_sync(0xffffffff, mxA, o));
                mxB = fmaxf(mxB, __shfl_xor_sync(0xffffffff, mxB, o));
            }
            float eA = __expf(sA - mxA), eB = __expf(sB - mxB);
            float uA = eA, uB = eB;
            #pragma unroll
            for (int o = 4; o <= 16; o <<= 1){
                uA += __shfl_xor_sync(0xffffffff, uA, o);
                uB += __shfl_xor_sync(0xffffffff, uB, o);
            }
            wA = __fdividef(eA, uA); wB = __fdividef(eB, uB);
        }

        // ---- value MLP on e ----
        mma_reg<8>(af, W1V, acc, lane);
        transition(acc, af, bs + 256, t);      // h2 -> af
        mma_reg<8>(af, W2V, acc, lane);

        // ---- v = tanh_acc(acc+b2); weighted sum over neighbors (g-dim) -> AA ----
        #pragma unroll
        for (int nt = 0; nt < 16; nt++){
            int c = nt * 8 + 2 * t;
            float b0 = bs[384 + c], b1 = bs[384 + c + 1];
            acc[nt][0] = tanh_acc(acc[nt][0] + b0) * wA;
            acc[nt][1] = tanh_acc(acc[nt][1] + b1) * wA;
            acc[nt][2] = tanh_acc(acc[nt][2] + b0) * wB;
            acc[nt][3] = tanh_acc(acc[nt][3] + b1) * wB;
        }
        #pragma unroll
        for (int o = 4; o <= 16; o <<= 1)
            #pragma unroll
            for (int nt = 0; nt < 16; nt++){
                acc[nt][0] += __shfl_xor_sync(0xffffffff, acc[nt][0], o);
                acc[nt][1] += __shfl_xor_sync(0xffffffff, acc[nt][1], o);
                acc[nt][2] += __shfl_xor_sync(0xffffffff, acc[nt][2], o);
                acc[nt][3] += __shfl_xor_sync(0xffffffff, acc[nt][3], o);
            }
        float* outA = AA + (size_t)(slab * 2) * 128;
        if (lane < 4){
            #pragma unroll
            for (int nt = 0; nt < 16; nt++)
                *(float2*)(outA + nt * 8 + 2 * t) = make_float2(acc[nt][0], acc[nt][1]);
        } else if (lane < 8){
            #pragma unroll
            for (int nt = 0; nt < 16; nt++)
                *(float2*)(outA + 128 + nt * 8 + 2 * t) = make_float2(acc[nt][2], acc[nt][3]);
        }
    }
}

// smem offsets (agent)
#define A_W1   0
#define A_W2   32768
#define A_BS   65536
#define A_SMEM 66560

// ============================================================================
// Agent MLP: AA (fp32) -> tanh(128->128) -> tanh(128->128) -> g_av (fp16)
// ============================================================================
__global__ void __launch_bounds__(512, 1)
agent_kernel(const float* __restrict__ X,
             const float* __restrict__ W1, const float* __restrict__ b1,
             const float* __restrict__ W2, const float* __restrict__ b2,
             __half* __restrict__ Y)
{
    extern __shared__ char sm[];
    uint4* Wp1 = (uint4*)(sm + A_W1);
    uint4* Wp2 = (uint4*)(sm + A_W2);
    float* bs  = (float*)(sm + A_BS);

    const int tid = threadIdx.x, w = tid >> 5, lane = tid & 31;
    const int g = lane >> 2, t = lane & 3;

    pack_w4(W1, Wp1, 8, 128, tid, 512);
    pack_w4(W2, Wp2, 8, 128, tid, 512);
    if (tid < 128){ bs[tid] = b1[tid]; bs[128 + tid] = b2[tid]; }
    __syncthreads();

    const int NSLAB = BATCHN / 16;            // 4096
    const int step  = gridDim.x * 16;

    for (int slab = blockIdx.x * 16 + w; slab < NSLAB; slab += step){
        const int row0 = slab * 16;
        uint32_t af[8][4];
        {
            const float2* pA = (const float2*)(X + (size_t)(row0 + g) * 128);
            const float2* pB = (const float2*)(X + (size_t)(row0 + g + 8) * 128);
            #pragma unroll
            for (int ks = 0; ks < 8; ks++){
                float2 a0 = pA[ks * 8 + t],     b0v = pB[ks * 8 + t];
                float2 a2 = pA[ks * 8 + t + 4], b2v = pB[ks * 8 + t + 4];
                af[ks][0] = pack2(a0.x, a0.y);
                af[ks][1] = pack2(b0v.x, b0v.y);
                af[ks][2] = pack2(a2.x, a2.y);
                af[ks][3] = pack2(b2v.x, b2v.y);
            }
        }
        float acc[16][4];
        mma_reg<8>(af, Wp1, acc, lane);
        transition(acc, af, bs, t);
        mma_reg<8>(af, Wp2, acc, lane);
        {
            __half* y0 = Y + (size_t)(row0 + g) * 128;
            __half* y1 = Y + (size_t)(row0 + g + 8) * 128;
            #pragma unroll
            for (int nt = 0; nt < 16; nt++){
                int c = nt * 8 + 2 * t;
                float b0 = bs[128 + c], b1v = bs[128 + c + 1];
                *(__half2*)(y0 + c) = __floats2half2_rn(tanh_acc(acc[nt][0] + b0),
                                                        tanh_acc(acc[nt][1] + b1v));
                *(__half2*)(y1 + c) = __floats2half2_rn(tanh_acc(acc[nt][2] + b0),
                                                        tanh_acc(acc[nt][3] + b1v));
            }
        }
    }
}

// ============================================================================
// Per-group multi-head attention (8 heads x 16 dims over 8 agents) + tile x8.
// ============================================================================
__global__ void __launch_bounds__(128)
mha_kernel(const float* __restrict__ AA, const __half* __restrict__ AV,
           float* __restrict__ out)
{
    __shared__ float ks[8][128];
    __shared__ float vs[8][128];
    const int g = blockIdx.x;
    const int j = threadIdx.x;
    const size_t base = (size_t)g * 8 * 128;

    #pragma unroll
    for (int a = 0; a < 8; a++){
        ks[a][j] = AA[base + a * 128 + j];
        vs[a][j] = __half2float(AV[base + a * 128 + j]);
    }
    __syncthreads();

    float q = 0.0f;
    #pragma unroll
    for (int a = 0; a < 8; a++) q += ks[a][j];
    q *= 0.03125f;                            // mean(1/8) * rsqrt(16)

    float s[8];
    #pragma unroll
    for (int a = 0; a < 8; a++){
        float p = q * ks[a][j];
        p += __shfl_xor_sync(0xffffffff, p, 8);
        p += __shfl_xor_sync(0xffffffff, p, 4);
        p += __shfl_xor_sync(0xffffffff, p, 2);
        p += __shfl_xor_sync(0xffffffff, p, 1);
        s[a] = p;
    }
    float mx = s[0];
    #pragma unroll
    for (int a = 1; a < 8; a++) mx = fmaxf(mx, s[a]);
    float wv[8], wsum = 0.0f;
    #pragma unroll
    for (int a = 0; a < 8; a++){ wv[a] = __expf(s[a] - mx); wsum += wv[a]; }
    const float inv = 1.0f / wsum;

    float o = 0.0f;
    #pragma unroll
    for (int a = 0; a < 8; a++) o += wv[a] * vs[a][j];
    o *= inv;

    #pragma unroll
    for (int tt = 0; tt < 8; tt++)
        out[((size_t)(tt * NGRP + g)) * 128 + j] = o;
}

// ============================================================================
extern "C" void kernel_launch(void* const* d_in, const int* in_sizes, int n_in,
                              void* d_out, int out_size)
{
    const float* obs = (const float*)d_in[0];
    const float* eW1 = (const float*)d_in[1];
    const float* eb1 = (const float*)d_in[2];
    const float* eW2 = (const float*)d_in[3];
    const float* eb2 = (const float*)d_in[4];
    const float* vW1 = (const float*)d_in[5];
    const float* vb1 = (const float*)d_in[6];
    const float* vW2 = (const float*)d_in[7];
    const float* vb2 = (const float*)d_in[8];
    const float* aW1 = (const float*)d_in[9];
    const float* ab1 = (const float*)d_in[10];
    const float* aW2 = (const float*)d_in[11];
    const float* ab2 = (const float*)d_in[12];

    float* out = (float*)d_out;                 // multi_head_attention
    float* AA  = out + (size_t)BATCHN * 128;    // agent_attention

    void* pav; cudaGetSymbolAddress(&pav, g_av);
    __half* av_g = (__half*)pav;

    cudaFuncSetAttribute(fused_ev_kernel, cudaFuncAttributeMaxDynamicSharedMemorySize, F_SMEM);
    cudaFuncSetAttribute(agent_kernel,    cudaFuncAttributeMaxDynamicSharedMemorySize, A_SMEM);

    fused_ev_kernel<<<148, 512, F_SMEM>>>(obs, eW1, eb1, eW2, eb2,
                                          vW1, vb1, vW2, vb2, AA);
    agent_kernel<<<148, 512, A_SMEM>>>(AA, aW1, ab1, aW2, ab2, av_g);
    mha_kernel<<<NGRP, 128>>>(AA, av_g, out);
}